// round 2
// baseline (speedup 1.0000x reference)
#include <cuda_runtime.h>
#include <cuda_fp16.h>

#define H    1024
#define HH   1025
#define G3   3075
#define TQ   512
#define TT   4608
#define KP   1088
#define NCTA 148
#define NTHR 256
#define TOT_OUT 2049   // yf[0..1024] + yb[0..1023]

__device__ float  g_gh [(size_t)TT * (2 * G3)];
__device__ float  g_h0 [(size_t)TT * 2050];
__device__ __half g_A16[(size_t)TT * 2 * KP];
__device__ __half g_W16[(size_t)2 * G3 * KP];
__device__ float  g_yfx[TT];
__device__ int    g_bar[TT];

__global__ void zero_bar_kernel() {
    int i = blockIdx.x * blockDim.x + threadIdx.x;
    if (i < TT) g_bar[i] = 0;
}

__global__ void __launch_bounds__(NTHR) prep_h0_kernel(
    const float* __restrict__ e_q, const float* __restrict__ e_p,
    const float* __restrict__ f_s, const float* __restrict__ f_e)
{
    int t = blockIdx.x, tid = threadIdx.x;
    for (int i = tid; i < 2050; i += NTHR) {
        float v;
        if (t < TQ) v = (i < 2048) ? e_q[(size_t)t * 2048 + i] : 0.f;
        else {
            int pt = t - TQ;
            v = (i < 2048) ? e_p[(size_t)pt * 2048 + i] : (i == 2048 ? f_s[pt] : f_e[pt]);
        }
        g_h0[(size_t)t * 2050 + i] = v;
        int d = (i >= HH) ? 1 : 0;
        g_A16[(size_t)t * (2 * KP) + (size_t)d * KP + (i - d * HH)] = __float2half_rn(v);
    }
    for (int i = tid; i < 2 * (KP - HH); i += NTHR) {   // zero K-padding
        int d = (i < (KP - HH)) ? 0 : 1;
        int k = HH + (i - d * (KP - HH));
        g_A16[(size_t)t * (2 * KP) + (size_t)d * KP + k] = __float2half_rn(0.f);
    }
}

__global__ void __launch_bounds__(NTHR) prep_whh_kernel(
    const float* __restrict__ Whh_f, const float* __restrict__ Whh_b)
{
    int r = blockIdx.x, d = r / G3, n = r % G3;
    const float* W = d ? Whh_b : Whh_f;
    for (int k = threadIdx.x; k < KP; k += NTHR)
        g_W16[(size_t)r * KP + k] = __float2half_rn(k < HH ? W[(size_t)n * HH + k] : 0.f);
}

__device__ __forceinline__ unsigned smem_u32(const void* p) {
    return (unsigned)__cvta_generic_to_shared(p);
}
__device__ __forceinline__ void ldmx4(unsigned& r0, unsigned& r1, unsigned& r2, unsigned& r3,
                                      unsigned a) {
    asm volatile("ldmatrix.sync.aligned.m8n8.x4.shared.b16 {%0,%1,%2,%3}, [%4];"
                 : "=r"(r0), "=r"(r1), "=r"(r2), "=r"(r3) : "r"(a));
}
__device__ __forceinline__ void mma16816(float* c, const unsigned* a, const unsigned* b) {
    asm volatile("mma.sync.aligned.m16n8k16.row.col.f32.f16.f16.f32 "
                 "{%0,%1,%2,%3},{%4,%5,%6,%7},{%8,%9},{%0,%1,%2,%3};"
                 : "+f"(c[0]), "+f"(c[1]), "+f"(c[2]), "+f"(c[3])
                 : "r"(a[0]), "r"(a[1]), "r"(a[2]), "r"(a[3]), "r"(b[0]), "r"(b[1]));
}

// grid (49 n-tiles, 36 m-tiles, 2 dirs); CTA tile 128x64, warp tile 32x32
__global__ void __launch_bounds__(NTHR) gh_gemm_kernel(
    const float* __restrict__ bhh_f, const float* __restrict__ bhh_b)
{
    const int d = blockIdx.z, m0 = blockIdx.y * 128, n0 = blockIdx.x * 64;
    __shared__ __half As[128][72];
    __shared__ __half Bs[64][72];
    int tid = threadIdx.x, lane = tid & 31, warp = tid >> 5;
    int wm = warp >> 1, wn = warp & 1;
    float c[2][4][4];
    #pragma unroll
    for (int a = 0; a < 2; a++)
        #pragma unroll
        for (int b = 0; b < 4; b++)
            #pragma unroll
            for (int e = 0; e < 4; e++) c[a][b][e] = 0.f;

    const __half* Bg = g_W16 + (size_t)d * G3 * KP;
    for (int k0 = 0; k0 < KP; k0 += 64) {
        #pragma unroll
        for (int it = 0; it < 4; it++) {
            int idx = it * NTHR + tid, row = idx >> 3, q = idx & 7;
            *(uint4*)&As[row][q * 8] =
                *(const uint4*)(g_A16 + (size_t)(m0 + row) * (2 * KP) + (size_t)d * KP + k0 + q * 8);
        }
        #pragma unroll
        for (int it = 0; it < 2; it++) {
            int idx = it * NTHR + tid, row = idx >> 3, q = idx & 7;
            int n = n0 + row;
            uint4 v = make_uint4(0u, 0u, 0u, 0u);
            if (n < G3) v = *(const uint4*)(Bg + (size_t)n * KP + k0 + q * 8);
            *(uint4*)&Bs[row][q * 8] = v;
        }
        __syncthreads();
        #pragma unroll
        for (int ks = 0; ks < 4; ks++) {
            unsigned a[2][4], b[2][4];
            #pragma unroll
            for (int mf = 0; mf < 2; mf++)
                ldmx4(a[mf][0], a[mf][1], a[mf][2], a[mf][3],
                      smem_u32(&As[wm * 32 + mf * 16 + (lane & 15)][ks * 16 + (lane >> 4) * 8]));
            #pragma unroll
            for (int nf2 = 0; nf2 < 2; nf2++) {
                int grp = lane >> 3, l = lane & 7;
                ldmx4(b[nf2][0], b[nf2][1], b[nf2][2], b[nf2][3],
                      smem_u32(&Bs[wn * 32 + nf2 * 16 + l + (grp >> 1) * 8][ks * 16 + (grp & 1) * 8]));
            }
            #pragma unroll
            for (int mf = 0; mf < 2; mf++)
                #pragma unroll
                for (int nf = 0; nf < 4; nf++) {
                    unsigned bb[2] = { b[nf >> 1][(nf & 1) * 2], b[nf >> 1][(nf & 1) * 2 + 1] };
                    mma16816(c[mf][nf], a[mf], bb);
                }
        }
        __syncthreads();
    }
    const float* bhh = d ? bhh_b : bhh_f;
    #pragma unroll
    for (int mf = 0; mf < 2; mf++)
        #pragma unroll
        for (int nf = 0; nf < 4; nf++) {
            int mrow = m0 + wm * 32 + mf * 16 + (lane >> 2);
            int ncol = n0 + wn * 32 + nf * 8 + (lane & 3) * 2;
            float* p1 = g_gh + (size_t)mrow * (2 * G3) + (size_t)d * G3;
            float* p2 = g_gh + (size_t)(mrow + 8) * (2 * G3) + (size_t)d * G3;
            if (ncol < G3)     { p1[ncol]     = c[mf][nf][0] + bhh[ncol];
                                 p2[ncol]     = c[mf][nf][2] + bhh[ncol]; }
            if (ncol + 1 < G3) { p1[ncol + 1] = c[mf][nf][1] + bhh[ncol + 1];
                                 p2[ncol + 1] = c[mf][nf][3] + bhh[ncol + 1]; }
        }
}

#define SMEM_W_BYTES 86016
#define SMEM_X_OFF   SMEM_W_BYTES
#define SMEM_D_OFF   (SMEM_W_BYTES + 4096)
#define SMEM_B_OFF   (SMEM_D_OFF + 192)
#define SCAN_SMEM    (SMEM_B_OFF + 192)

__global__ void __launch_bounds__(NTHR, 1) scan_kernel(
    const float* __restrict__ Wih_f, const float* __restrict__ Wih_b,
    const float* __restrict__ bih_f, const float* __restrict__ bih_b,
    float* __restrict__ out)
{
    extern __shared__ char smem_raw[];
    __half* wsm = (__half*)smem_raw;
    float*  xsm = (float*)(smem_raw + SMEM_X_OFF);
    float*  dsm = (float*)(smem_raw + SMEM_D_OFF);
    float*  bsm = (float*)(smem_raw + SMEM_B_OFF);

    const int tid = threadIdx.x, lane = tid & 31, warp = tid >> 5;
    const int cta = blockIdx.x;
    const int ostart = (cta * TOT_OUT) / NCTA;
    const int oend   = ((cta + 1) * TOT_OUT) / NCTA;
    const int nout = oend - ostart, nr3 = nout * 3;

    for (int r = 0; r < nr3; r++) {               // stage Wih shard -> SMEM fp16
        int o = r / 3, g = r % 3, gidx = ostart + o;
        int dir = (gidx >= HH) ? 1 : 0, j = gidx - dir * HH;
        const float* src = (dir ? Wih_b : Wih_f) + (size_t)(g * HH + j) * H;
        for (int k = tid; k < H; k += NTHR) wsm[r * H + k] = __float2half_rn(src[k]);
        if (tid == 0) bsm[r] = (dir ? bih_b : bih_f)[g * HH + j];
    }
    __syncthreads();

    int gstep = 0;
    for (int s = 0; s < 2; s++) {
        const int Ts = s ? (TT - TQ) : TQ;
        const int tokbase = s ? TQ : 0;
        for (int t = 0; t < Ts; t++, gstep++) {
            const int token = tokbase + t;

            float ghv0 = 0.f, ghv1 = 0.f, ghv2 = 0.f, hv = 0.f;
            if (tid < nout) {
                int gidx = ostart + tid;
                int dir = (gidx >= HH) ? 1 : 0, j = gidx - dir * HH;
                const float* ghp = g_gh + (size_t)token * (2 * G3) + (size_t)dir * G3 + j;
                ghv0 = ghp[0]; ghv1 = ghp[HH]; ghv2 = ghp[2 * HH];
                hv = g_h0[(size_t)token * 2050 + gidx];
            }

            if (t == 0) {
                for (int j = tid; j < H; j += NTHR) xsm[j] = 0.f;
            } else {
                const float* prev = out + (size_t)(token - 1) * 2048;
                for (int j = tid; j < H; j += NTHR) {
                    float a = prev[j];
                    float b = (j == 0) ? *(volatile float*)&g_yfx[token - 1] : prev[1023 + j];
                    xsm[j] = a + b;
                }
            }
            __syncthreads();

            float xr[32];
            #pragma unroll
            for (int cc = 0; cc < 8; cc++) {
                float4 v = *(const float4*)&xsm[cc * 128 + lane * 4];
                xr[cc * 4] = v.x; xr[cc * 4 + 1] = v.y; xr[cc * 4 + 2] = v.z; xr[cc * 4 + 3] = v.w;
            }
            for (int r = warp; r < nr3; r += 8) {
                const __half* wr = wsm + r * H;
                float acc = 0.f;
                #pragma unroll
                for (int cc = 0; cc < 8; cc++) {
                    uint2 u = *(const uint2*)&wr[cc * 128 + lane * 4];
                    float2 f01 = __half22float2(*(__half2*)&u.x);
                    float2 f23 = __half22float2(*(__half2*)&u.y);
                    acc = fmaf(f01.x, xr[cc * 4], acc);
                    acc = fmaf(f01.y, xr[cc * 4 + 1], acc);
                    acc = fmaf(f23.x, xr[cc * 4 + 2], acc);
                    acc = fmaf(f23.y, xr[cc * 4 + 3], acc);
                }
                #pragma unroll
                for (int off = 16; off; off >>= 1)
                    acc += __shfl_xor_sync(0xffffffffu, acc, off);
                if (lane == 0) dsm[r] = acc + bsm[r];
            }
            __syncthreads();

            if (tid < nout) {
                float iR = dsm[tid * 3], iZ = dsm[tid * 3 + 1], iN = dsm[tid * 3 + 2];
                float rg = 1.f / (1.f + __expf(-(iR + ghv0)));
                float zg = 1.f / (1.f + __expf(-(iZ + ghv1)));
                float ng = tanhf(iN + rg * ghv2);
                float y = (1.f - zg) * ng + zg * hv;
                int gidx = ostart + tid;
                if (gidx < HH) {
                    if (gidx < H) out[(size_t)token * 2048 + gidx] = y;
                    else          g_yfx[token] = y;
                } else {
                    out[(size_t)token * 2048 + 1024 + (gidx - HH)] = y;
                }
            }

            __syncthreads();
            if (tid == 0) {
                __threadfence();
                atomicAdd(&g_bar[gstep], 1);
                while (((volatile int*)g_bar)[gstep] < NCTA) { }
                __threadfence();
            }
            __syncthreads();
        }
    }
}

extern "C" void kernel_launch(void* const* d_in, const int* in_sizes, int n_in,
                              void* d_out, int out_size)
{
    const float* e_q   = (const float*)d_in[0];
    const float* e_p   = (const float*)d_in[1];
    const float* f_s   = (const float*)d_in[2];
    const float* f_e   = (const float*)d_in[3];
    const float* Wih_f = (const float*)d_in[4];
    const float* Whh_f = (const float*)d_in[5];
    const float* bih_f = (const float*)d_in[6];
    const float* bhh_f = (const float*)d_in[7];
    const float* Wih_b = (const float*)d_in[8];
    const float* Whh_b = (const float*)d_in[9];
    const float* bih_b = (const float*)d_in[10];
    const float* bhh_b = (const float*)d_in[11];

    cudaFuncSetAttribute(scan_kernel, cudaFuncAttributeMaxDynamicSharedMemorySize, SCAN_SMEM);

    zero_bar_kernel<<<(TT + 255) / 256, 256>>>();
    prep_h0_kernel<<<TT, NTHR>>>(e_q, e_p, f_s, f_e);
    prep_whh_kernel<<<2 * G3, NTHR>>>(Whh_f, Whh_b);
    gh_gemm_kernel<<<dim3(49, 36, 2), NTHR>>>(bhh_f, bhh_b);
    scan_kernel<<<NCTA, NTHR, SCAN_SMEM>>>(Wih_f, Wih_b, bih_f, bih_b, (float*)d_out);
}

// round 3
// speedup vs baseline: 1.7298x; 1.7298x over previous
#include <cuda_runtime.h>
#include <cuda_fp16.h>

#define H    1024
#define HH   1025
#define G3   3075
#define TQ   512
#define TT   4608
#define KP   1088
#define NTHR 256
#define NC   129      // CTAs per chain
#define OPC  16       // outputs per CTA (2 per warp)

__device__ float  g_gh [(size_t)TT * (2 * G3)];
__device__ float  g_h0 [(size_t)TT * 2050];
__device__ __half g_A16[(size_t)TT * 2 * KP];
__device__ __half g_W16[(size_t)2 * G3 * KP];
__device__ float  g_yfx[TT];
__device__ int    g_bar[8192];          // [0..4095] p-chain, [4096..] q-chain

__global__ void zero_bar_kernel() {
    int i = blockIdx.x * blockDim.x + threadIdx.x;
    if (i < 8192) g_bar[i] = 0;
}

__global__ void __launch_bounds__(NTHR) prep_h0_kernel(
    const float* __restrict__ e_q, const float* __restrict__ e_p,
    const float* __restrict__ f_s, const float* __restrict__ f_e)
{
    int t = blockIdx.x, tid = threadIdx.x;
    for (int i = tid; i < 2050; i += NTHR) {
        float v;
        if (t < TQ) v = (i < 2048) ? e_q[(size_t)t * 2048 + i] : 0.f;
        else {
            int pt = t - TQ;
            v = (i < 2048) ? e_p[(size_t)pt * 2048 + i] : (i == 2048 ? f_s[pt] : f_e[pt]);
        }
        g_h0[(size_t)t * 2050 + i] = v;
        int d = (i >= HH) ? 1 : 0;
        g_A16[(size_t)t * (2 * KP) + (size_t)d * KP + (i - d * HH)] = __float2half_rn(v);
    }
    for (int i = tid; i < 2 * (KP - HH); i += NTHR) {
        int d = (i < (KP - HH)) ? 0 : 1;
        int k = HH + (i - d * (KP - HH));
        g_A16[(size_t)t * (2 * KP) + (size_t)d * KP + k] = __float2half_rn(0.f);
    }
}

__global__ void __launch_bounds__(NTHR) prep_whh_kernel(
    const float* __restrict__ Whh_f, const float* __restrict__ Whh_b)
{
    int r = blockIdx.x, d = r / G3, n = r % G3;
    const float* W = d ? Whh_b : Whh_f;
    for (int k = threadIdx.x; k < KP; k += NTHR)
        g_W16[(size_t)r * KP + k] = __float2half_rn(k < HH ? W[(size_t)n * HH + k] : 0.f);
}

__device__ __forceinline__ unsigned smem_u32(const void* p) {
    return (unsigned)__cvta_generic_to_shared(p);
}
__device__ __forceinline__ void ldmx4(unsigned& r0, unsigned& r1, unsigned& r2, unsigned& r3,
                                      unsigned a) {
    asm volatile("ldmatrix.sync.aligned.m8n8.x4.shared.b16 {%0,%1,%2,%3}, [%4];"
                 : "=r"(r0), "=r"(r1), "=r"(r2), "=r"(r3) : "r"(a));
}
__device__ __forceinline__ void mma16816(float* c, const unsigned* a, const unsigned* b) {
    asm volatile("mma.sync.aligned.m16n8k16.row.col.f32.f16.f16.f32 "
                 "{%0,%1,%2,%3},{%4,%5,%6,%7},{%8,%9},{%0,%1,%2,%3};"
                 : "+f"(c[0]), "+f"(c[1]), "+f"(c[2]), "+f"(c[3])
                 : "r"(a[0]), "r"(a[1]), "r"(a[2]), "r"(a[3]), "r"(b[0]), "r"(b[1]));
}

__global__ void __launch_bounds__(NTHR) gh_gemm_kernel(
    const float* __restrict__ bhh_f, const float* __restrict__ bhh_b)
{
    const int d = blockIdx.z, m0 = blockIdx.y * 128, n0 = blockIdx.x * 64;
    __shared__ __half As[128][72];
    __shared__ __half Bs[64][72];
    int tid = threadIdx.x, lane = tid & 31, warp = tid >> 5;
    int wm = warp >> 1, wn = warp & 1;
    float c[2][4][4];
    #pragma unroll
    for (int a = 0; a < 2; a++)
        #pragma unroll
        for (int b = 0; b < 4; b++)
            #pragma unroll
            for (int e = 0; e < 4; e++) c[a][b][e] = 0.f;

    const __half* Bg = g_W16 + (size_t)d * G3 * KP;
    for (int k0 = 0; k0 < KP; k0 += 64) {
        #pragma unroll
        for (int it = 0; it < 4; it++) {
            int idx = it * NTHR + tid, row = idx >> 3, q = idx & 7;
            *(uint4*)&As[row][q * 8] =
                *(const uint4*)(g_A16 + (size_t)(m0 + row) * (2 * KP) + (size_t)d * KP + k0 + q * 8);
        }
        #pragma unroll
        for (int it = 0; it < 2; it++) {
            int idx = it * NTHR + tid, row = idx >> 3, q = idx & 7;
            int n = n0 + row;
            uint4 v = make_uint4(0u, 0u, 0u, 0u);
            if (n < G3) v = *(const uint4*)(Bg + (size_t)n * KP + k0 + q * 8);
            *(uint4*)&Bs[row][q * 8] = v;
        }
        __syncthreads();
        #pragma unroll
        for (int ks = 0; ks < 4; ks++) {
            unsigned a[2][4], b[2][4];
            #pragma unroll
            for (int mf = 0; mf < 2; mf++)
                ldmx4(a[mf][0], a[mf][1], a[mf][2], a[mf][3],
                      smem_u32(&As[wm * 32 + mf * 16 + (lane & 15)][ks * 16 + (lane >> 4) * 8]));
            #pragma unroll
            for (int nf2 = 0; nf2 < 2; nf2++) {
                int grp = lane >> 3, l = lane & 7;
                ldmx4(b[nf2][0], b[nf2][1], b[nf2][2], b[nf2][3],
                      smem_u32(&Bs[wn * 32 + nf2 * 16 + l + (grp >> 1) * 8][ks * 16 + (grp & 1) * 8]));
            }
            #pragma unroll
            for (int mf = 0; mf < 2; mf++)
                #pragma unroll
                for (int nf = 0; nf < 4; nf++) {
                    unsigned bb[2] = { b[nf >> 1][(nf & 1) * 2], b[nf >> 1][(nf & 1) * 2 + 1] };
                    mma16816(c[mf][nf], a[mf], bb);
                }
        }
        __syncthreads();
    }
    const float* bhh = d ? bhh_b : bhh_f;
    #pragma unroll
    for (int mf = 0; mf < 2; mf++)
        #pragma unroll
        for (int nf = 0; nf < 4; nf++) {
            int mrow = m0 + wm * 32 + mf * 16 + (lane >> 2);
            int ncol = n0 + wn * 32 + nf * 8 + (lane & 3) * 2;
            float* p1 = g_gh + (size_t)mrow * (2 * G3) + (size_t)d * G3;
            float* p2 = g_gh + (size_t)(mrow + 8) * (2 * G3) + (size_t)d * G3;
            if (ncol < G3)     { p1[ncol]     = c[mf][nf][0] + bhh[ncol];
                                 p2[ncol]     = c[mf][nf][2] + bhh[ncol]; }
            if (ncol + 1 < G3) { p1[ncol + 1] = c[mf][nf][1] + bhh[ncol + 1];
                                 p2[ncol + 1] = c[mf][nf][3] + bhh[ncol + 1]; }
        }
}

// ---------------- barrier primitives ----------------
__device__ __forceinline__ int ld_acq_gpu(const int* p) {
    int v;
    asm volatile("ld.acquire.gpu.global.s32 %0, [%1];" : "=r"(v) : "l"(p) : "memory");
    return v;
}
__device__ __forceinline__ void red_rel_gpu(int* p) {
    asm volatile("red.release.gpu.global.add.s32 [%0], 1;" :: "l"(p) : "memory");
}
__device__ __forceinline__ void st_rel_cta(int* p, int v) {
    asm volatile("st.release.cta.s32 [%0], %1;" :: "l"(p), "r"(v) : "memory");
}
__device__ __forceinline__ int ld_acq_cta(const int* p) {
    int v;
    asm volatile("ld.acquire.cta.s32 %0, [%1];" : "=r"(v) : "l"(p) : "memory");
    return v;
}

#define SCAN_SMEM (48 * H * 2)   // 98304 B of fp16 weights

__global__ void __launch_bounds__(NTHR, 2) scan_kernel(
    const float* __restrict__ Wih_f, const float* __restrict__ Wih_b,
    const float* __restrict__ bih_f, const float* __restrict__ bih_b,
    float* __restrict__ out)
{
    extern __shared__ __half wsm[];
    __shared__ float bsm[48];
    __shared__ int s_step;

    const int tid = threadIdx.x, lane = tid & 31, warp = tid >> 5;
    const int chain = (blockIdx.x >= NC) ? 1 : 0;       // 0 = p (long), 1 = q
    const int c = blockIdx.x - chain * NC;
    const int ostart = c * OPC;
    int* bar = g_bar + chain * 4096;
    const int base = chain ? 0 : TQ;
    const int Ts   = chain ? TQ : (TT - TQ);

    // ---- stage this warp's 6 weight rows (fp16) + biases ----
    #pragma unroll
    for (int r = 0; r < 6; r++) {
        int o = 2 * warp + r / 3, g = r % 3;
        int gidx = ostart + o; if (gidx > 2048) gidx = 2048;
        int dir = (gidx >= HH) ? 1 : 0, j = gidx - dir * HH;
        const float* src = (dir ? Wih_b : Wih_f) + (size_t)(g * HH + j) * H;
        __half* drow = wsm + (warp * 6 + r) * H;
        for (int k = lane; k < H; k += 32) drow[k] = __float2half_rn(src[k]);
        if (lane == 0) bsm[warp * 6 + r] = (dir ? bih_b : bih_f)[g * HH + j];
    }
    if (tid == 0) s_step = 0;
    __syncthreads();

    const bool gate_lane = (lane == 0 || lane == 16);
    const int my_o = 2 * warp + (lane >> 4);
    const int gidx_me = ostart + my_o;
    const int gclamp = (gidx_me > 2048) ? 2048 : gidx_me;
    const int gdir = (gclamp >= HH) ? 1 : 0;
    const size_t gh_off0 = (size_t)gdir * G3 + (gclamp - gdir * HH);

    for (int i = 0; i < Ts; i++) {
        const int token = base + i;

        // prefetch gh + h0 (carry-independent) before the wait
        float ghR = 0.f, ghZ = 0.f, ghN = 0.f, hv = 0.f;
        if (gate_lane) {
            const float* ghp = g_gh + (size_t)token * (2 * G3) + gh_off0;
            ghR = ghp[0]; ghZ = ghp[HH]; ghN = ghp[2 * HH];
            hv  = g_h0[(size_t)token * 2050 + gclamp];
        }

        if (i > 0) {
            if (warp == 0) {
                while (ld_acq_gpu(&bar[i - 1]) < NC) { }
                if (lane == 0) st_rel_cta(&s_step, i);
            } else {
                while (ld_acq_cta(&s_step) < i) { }
            }
        }

        // ---- build x in registers ----
        float xv[32];
        if (i == 0) {
            #pragma unroll
            for (int k2 = 0; k2 < 32; k2++) xv[k2] = 0.f;
        } else {
            const float* prev = out + (size_t)(token - 1) * 2048;
            float yfxv = g_yfx[token - 1];
            #pragma unroll
            for (int cc = 0; cc < 8; cc++) {
                int k = cc * 128 + lane * 4;
                float4 a  = *(const float4*)(prev + k);
                float4 cv = *(const float4*)(prev + 1024 + k);
                float wp = __shfl_up_sync(0xffffffffu, cv.w, 1);
                if (lane == 0) wp = (cc == 0) ? yfxv : prev[1023 + cc * 128];
                xv[cc * 4 + 0] = a.x + wp;
                xv[cc * 4 + 1] = a.y + cv.x;
                xv[cc * 4 + 2] = a.z + cv.y;
                xv[cc * 4 + 3] = a.w + cv.z;
            }
        }

        // ---- GEMV: 6 rows, fp16 weights from SMEM, fp32 accum ----
        float acc[6];
        const __half* wb = wsm + warp * 6 * H;
        #pragma unroll
        for (int r = 0; r < 6; r++) {
            float a = 0.f;
            #pragma unroll
            for (int cc = 0; cc < 8; cc++) {
                uint2 u = *(const uint2*)(wb + r * H + cc * 128 + lane * 4);
                float2 f01 = __half22float2(*(__half2*)&u.x);
                float2 f23 = __half22float2(*(__half2*)&u.y);
                a = fmaf(f01.x, xv[cc * 4 + 0], a);
                a = fmaf(f01.y, xv[cc * 4 + 1], a);
                a = fmaf(f23.x, xv[cc * 4 + 2], a);
                a = fmaf(f23.y, xv[cc * 4 + 3], a);
            }
            acc[r] = a;
        }
        #pragma unroll
        for (int r = 0; r < 6; r++)
            #pragma unroll
            for (int off = 16; off; off >>= 1)
                acc[r] += __shfl_xor_sync(0xffffffffu, acc[r], off);

        // ---- gates + store (lanes 0 and 16 each own one output) ----
        if (gate_lane && gidx_me < 2049) {
            int rb = (lane >> 4) * 3;
            float iR = acc[rb]     + bsm[warp * 6 + rb];
            float iZ = acc[rb + 1] + bsm[warp * 6 + rb + 1];
            float iN = acc[rb + 2] + bsm[warp * 6 + rb + 2];
            float rg = 1.f / (1.f + __expf(-(iR + ghR)));
            float zg = 1.f / (1.f + __expf(-(iZ + ghZ)));
            float ng = tanhf(iN + rg * ghN);
            float y = (1.f - zg) * ng + zg * hv;
            if (gidx_me < 1024)       out[(size_t)token * 2048 + gidx_me] = y;
            else if (gidx_me == 1024) g_yfx[token] = y;
            else                      out[(size_t)token * 2048 + gidx_me - 1] = y;
        }

        __syncthreads();
        if (tid == 0) red_rel_gpu(&bar[i]);
    }
}

extern "C" void kernel_launch(void* const* d_in, const int* in_sizes, int n_in,
                              void* d_out, int out_size)
{
    const float* e_q   = (const float*)d_in[0];
    const float* e_p   = (const float*)d_in[1];
    const float* f_s   = (const float*)d_in[2];
    const float* f_e   = (const float*)d_in[3];
    const float* Wih_f = (const float*)d_in[4];
    const float* Whh_f = (const float*)d_in[5];
    const float* bih_f = (const float*)d_in[6];
    const float* bhh_f = (const float*)d_in[7];
    const float* Wih_b = (const float*)d_in[8];
    const float* Whh_b = (const float*)d_in[9];
    const float* bih_b = (const float*)d_in[10];
    const float* bhh_b = (const float*)d_in[11];

    cudaFuncSetAttribute(scan_kernel, cudaFuncAttributeMaxDynamicSharedMemorySize, SCAN_SMEM);

    zero_bar_kernel<<<32, 256>>>();
    prep_h0_kernel<<<TT, NTHR>>>(e_q, e_p, f_s, f_e);
    prep_whh_kernel<<<2 * G3, NTHR>>>(Whh_f, Whh_b);
    gh_gemm_kernel<<<dim3(49, 36, 2), NTHR>>>(bhh_f, bhh_b);
    scan_kernel<<<2 * NC, NTHR, SCAN_SMEM>>>(Wih_f, Wih_b, bih_f, bih_b, (float*)d_out);
}

// round 8
// speedup vs baseline: 1.9064x; 1.1021x over previous
#include <cuda_runtime.h>
#include <cuda_fp16.h>

#define H    1024
#define HH   1025
#define G3   3075
#define TQ   512
#define TT   4608
#define KP   1088
#define NTHR 256
#define NC   129      // CTAs per chain
#define OPC  16       // outputs per CTA (2 per warp)

__device__ float  g_gh [(size_t)TT * (2 * G3)];
__device__ float  g_h0 [(size_t)TT * 2050];
__device__ __half g_A16[(size_t)TT * 2 * KP];
__device__ __half g_W16[(size_t)2 * G3 * KP];
__device__ float  g_yfx[TT];
__device__ int    g_bar[8192];

__global__ void zero_bar_kernel() {
    int i = blockIdx.x * blockDim.x + threadIdx.x;
    if (i < 8192) g_bar[i] = 0;
}

__global__ void __launch_bounds__(NTHR) prep_h0_kernel(
    const float* __restrict__ e_q, const float* __restrict__ e_p,
    const float* __restrict__ f_s, const float* __restrict__ f_e)
{
    int t = blockIdx.x, tid = threadIdx.x;
    for (int i = tid; i < 2050; i += NTHR) {
        float v;
        if (t < TQ) v = (i < 2048) ? e_q[(size_t)t * 2048 + i] : 0.f;
        else {
            int pt = t - TQ;
            v = (i < 2048) ? e_p[(size_t)pt * 2048 + i] : (i == 2048 ? f_s[pt] : f_e[pt]);
        }
        g_h0[(size_t)t * 2050 + i] = v;
        int d = (i >= HH) ? 1 : 0;
        g_A16[(size_t)t * (2 * KP) + (size_t)d * KP + (i - d * HH)] = __float2half_rn(v);
    }
    for (int i = tid; i < 2 * (KP - HH); i += NTHR) {
        int d = (i < (KP - HH)) ? 0 : 1;
        int k = HH + (i - d * (KP - HH));
        g_A16[(size_t)t * (2 * KP) + (size_t)d * KP + k] = __float2half_rn(0.f);
    }
}

__global__ void __launch_bounds__(NTHR) prep_whh_kernel(
    const float* __restrict__ Whh_f, const float* __restrict__ Whh_b)
{
    int r = blockIdx.x, d = r / G3, n = r % G3;
    const float* W = d ? Whh_b : Whh_f;
    for (int k = threadIdx.x; k < KP; k += NTHR)
        g_W16[(size_t)r * KP + k] = __float2half_rn(k < HH ? W[(size_t)n * HH + k] : 0.f);
}

__device__ __forceinline__ unsigned smem_u32(const void* p) {
    return (unsigned)__cvta_generic_to_shared(p);
}
__device__ __forceinline__ void ldmx4(unsigned& r0, unsigned& r1, unsigned& r2, unsigned& r3,
                                      unsigned a) {
    asm volatile("ldmatrix.sync.aligned.m8n8.x4.shared.b16 {%0,%1,%2,%3}, [%4];"
                 : "=r"(r0), "=r"(r1), "=r"(r2), "=r"(r3) : "r"(a));
}
__device__ __forceinline__ void mma16816(float* c, const unsigned* a, const unsigned* b) {
    asm volatile("mma.sync.aligned.m16n8k16.row.col.f32.f16.f16.f32 "
                 "{%0,%1,%2,%3},{%4,%5,%6,%7},{%8,%9},{%0,%1,%2,%3};"
                 : "+f"(c[0]), "+f"(c[1]), "+f"(c[2]), "+f"(c[3])
                 : "r"(a[0]), "r"(a[1]), "r"(a[2]), "r"(a[3]), "r"(b[0]), "r"(b[1]));
}

__global__ void __launch_bounds__(NTHR) gh_gemm_kernel(
    const float* __restrict__ bhh_f, const float* __restrict__ bhh_b)
{
    const int d = blockIdx.z, m0 = blockIdx.y * 128, n0 = blockIdx.x * 64;
    __shared__ __half As[128][72];
    __shared__ __half Bs[64][72];
    int tid = threadIdx.x, lane = tid & 31, warp = tid >> 5;
    int wm = warp >> 1, wn = warp & 1;
    float c[2][4][4];
    #pragma unroll
    for (int a = 0; a < 2; a++)
        #pragma unroll
        for (int b = 0; b < 4; b++)
            #pragma unroll
            for (int e = 0; e < 4; e++) c[a][b][e] = 0.f;

    const __half* Bg = g_W16 + (size_t)d * G3 * KP;
    for (int k0 = 0; k0 < KP; k0 += 64) {
        #pragma unroll
        for (int it = 0; it < 4; it++) {
            int idx = it * NTHR + tid, row = idx >> 3, q = idx & 7;
            *(uint4*)&As[row][q * 8] =
                *(const uint4*)(g_A16 + (size_t)(m0 + row) * (2 * KP) + (size_t)d * KP + k0 + q * 8);
        }
        #pragma unroll
        for (int it = 0; it < 2; it++) {
            int idx = it * NTHR + tid, row = idx >> 3, q = idx & 7;
            int n = n0 + row;
            uint4 v = make_uint4(0u, 0u, 0u, 0u);
            if (n < G3) v = *(const uint4*)(Bg + (size_t)n * KP + k0 + q * 8);
            *(uint4*)&Bs[row][q * 8] = v;
        }
        __syncthreads();
        #pragma unroll
        for (int ks = 0; ks < 4; ks++) {
            unsigned a[2][4], b[2][4];
            #pragma unroll
            for (int mf = 0; mf < 2; mf++)
                ldmx4(a[mf][0], a[mf][1], a[mf][2], a[mf][3],
                      smem_u32(&As[wm * 32 + mf * 16 + (lane & 15)][ks * 16 + (lane >> 4) * 8]));
            #pragma unroll
            for (int nf2 = 0; nf2 < 2; nf2++) {
                int grp = lane >> 3, l = lane & 7;
                ldmx4(b[nf2][0], b[nf2][1], b[nf2][2], b[nf2][3],
                      smem_u32(&Bs[wn * 32 + nf2 * 16 + l + (grp >> 1) * 8][ks * 16 + (grp & 1) * 8]));
            }
            #pragma unroll
            for (int mf = 0; mf < 2; mf++)
                #pragma unroll
                for (int nf = 0; nf < 4; nf++) {
                    unsigned bb[2] = { b[nf >> 1][(nf & 1) * 2], b[nf >> 1][(nf & 1) * 2 + 1] };
                    mma16816(c[mf][nf], a[mf], bb);
                }
        }
        __syncthreads();
    }
    const float* bhh = d ? bhh_b : bhh_f;
    #pragma unroll
    for (int mf = 0; mf < 2; mf++)
        #pragma unroll
        for (int nf = 0; nf < 4; nf++) {
            int mrow = m0 + wm * 32 + mf * 16 + (lane >> 2);
            int ncol = n0 + wn * 32 + nf * 8 + (lane & 3) * 2;
            float* p1 = g_gh + (size_t)mrow * (2 * G3) + (size_t)d * G3;
            float* p2 = g_gh + (size_t)(mrow + 8) * (2 * G3) + (size_t)d * G3;
            if (ncol < G3)     { p1[ncol]     = c[mf][nf][0] + bhh[ncol];
                                 p2[ncol]     = c[mf][nf][2] + bhh[ncol]; }
            if (ncol + 1 < G3) { p1[ncol + 1] = c[mf][nf][1] + bhh[ncol + 1];
                                 p2[ncol + 1] = c[mf][nf][3] + bhh[ncol + 1]; }
        }
}

// ---------------- barrier primitives ----------------
__device__ __forceinline__ int ld_acq_gpu(const int* p) {
    int v;
    asm volatile("ld.acquire.gpu.global.s32 %0, [%1];" : "=r"(v) : "l"(p) : "memory");
    return v;
}
__device__ __forceinline__ void red_rel_gpu(int* p) {
    asm volatile("red.release.gpu.global.add.s32 [%0], 1;" :: "l"(p) : "memory");
}
__device__ __forceinline__ void st_rel_cta(int* p, int v) {
    asm volatile("st.release.cta.s32 [%0], %1;" :: "l"(p), "r"(v) : "memory");
}
__device__ __forceinline__ int ld_acq_cta(const int* p) {
    int v;
    asm volatile("ld.acquire.cta.s32 %0, [%1];" : "=r"(v) : "l"(p) : "memory");
    return v;
}

// scan: 2 outputs per warp; rows 0-2 (output A) in registers, rows 3-5 (output B) in SMEM
__global__ void __launch_bounds__(NTHR, 2) scan_kernel(
    const float* __restrict__ Wih_f, const float* __restrict__ Wih_b,
    const float* __restrict__ bih_f, const float* __restrict__ bih_b,
    float* __restrict__ out)
{
    __shared__ __half wsm2[8 * 3 * 1024];   // 48 KB: 3 smem rows per warp
    __shared__ float bsm[48];
    __shared__ int s_step;

    const int tid = threadIdx.x, lane = tid & 31, warp = tid >> 5;
    const int chain = (blockIdx.x >= NC) ? 1 : 0;   // 0 = p (long), 1 = q
    const int c = blockIdx.x - chain * NC;
    const int ostart = c * OPC;
    int* bar = g_bar + chain * 4096;
    const int base = chain ? 0 : TQ;
    const int Ts   = chain ? TQ : (TT - TQ);

    // ---- stage weights: rows 0-2 -> regs, rows 3-5 -> SMEM ----
    __half2 wreg[3][16];
    #pragma unroll
    for (int r = 0; r < 6; r++) {
        int o = r / 3, g = r % 3;
        int gidx = ostart + 2 * warp + o; if (gidx > 2048) gidx = 2048;
        int dir = (gidx >= HH) ? 1 : 0, j = gidx - dir * HH;
        const float* src = (dir ? Wih_b : Wih_f) + (size_t)(g * HH + j) * H;
        if (r < 3) {
            #pragma unroll
            for (int cc = 0; cc < 4; cc++) {
                int k0 = cc * 256 + lane * 8;
                float4 f0 = *(const float4*)(src + k0);
                float4 f1 = *(const float4*)(src + k0 + 4);
                wreg[r][cc * 4 + 0] = __floats2half2_rn(f0.x, f0.y);
                wreg[r][cc * 4 + 1] = __floats2half2_rn(f0.z, f0.w);
                wreg[r][cc * 4 + 2] = __floats2half2_rn(f1.x, f1.y);
                wreg[r][cc * 4 + 3] = __floats2half2_rn(f1.z, f1.w);
            }
        } else {
            __half* dst = wsm2 + (warp * 3 + (r - 3)) * 1024;
            #pragma unroll
            for (int b = 0; b < 8; b++) {
                int k = b * 128 + lane * 4;
                float4 f = *(const float4*)(src + k);
                *(__half2*)&dst[k]     = __floats2half2_rn(f.x, f.y);
                *(__half2*)&dst[k + 2] = __floats2half2_rn(f.z, f.w);
            }
        }
        if (lane == 0) bsm[warp * 6 + r] = (dir ? bih_b : bih_f)[g * HH + j];
    }
    if (tid == 0) s_step = 0;
    __syncthreads();

    const bool gate_lane = (lane == 0 || lane == 16);
    const int gidx_me = ostart + 2 * warp + (lane >> 4);
    const int gclamp = (gidx_me > 2048) ? 2048 : gidx_me;
    const int gdir = (gclamp >= HH) ? 1 : 0;
    const size_t gh_off0 = (size_t)gdir * G3 + (gclamp - gdir * HH);

    for (int i = 0; i < Ts; i++) {
        const int token = base + i;

        // prefetch gh + h0 (carry-independent)
        float ghR = 0.f, ghZ = 0.f, ghN = 0.f, hv = 0.f;
        if (gate_lane) {
            const float* ghp = g_gh + (size_t)token * (2 * G3) + gh_off0;
            ghR = ghp[0]; ghZ = ghp[HH]; ghN = ghp[2 * HH];
            hv  = g_h0[(size_t)token * 2050 + gclamp];
        }

        if (i > 0) {
            if (warp == 0) {
                while (ld_acq_gpu(&bar[i - 1]) < NC) { }
                if (lane == 0) st_rel_cta(&s_step, i);
            } else {
                while (ld_acq_cta(&s_step) < i) { }
            }
        }

        // ---- build x as half2 (8 consecutive elems per lane per cc-block) ----
        __half2 xh[16];
        if (i == 0) {
            #pragma unroll
            for (int k2 = 0; k2 < 16; k2++) xh[k2] = __float2half2_rn(0.f);
        } else {
            const float* prev = out + (size_t)(token - 1) * 2048;
            float yfxv = *(volatile float*)&g_yfx[token - 1];
            #pragma unroll
            for (int cc = 0; cc < 4; cc++) {
                int k0 = cc * 256 + lane * 8;
                float4 a0 = *(const float4*)(prev + k0);
                float4 a1 = *(const float4*)(prev + k0 + 4);
                float4 c0 = *(const float4*)(prev + 1024 + k0);
                float4 c1 = *(const float4*)(prev + 1024 + k0 + 4);
                float carry = __shfl_up_sync(0xffffffffu, c1.w, 1);
                if (lane == 0) carry = (cc == 0) ? yfxv : prev[1023 + cc * 256];
                xh[cc * 4 + 0] = __floats2half2_rn(a0.x + carry, a0.y + c0.x);
                xh[cc * 4 + 1] = __floats2half2_rn(a0.z + c0.y,  a0.w + c0.z);
                xh[cc * 4 + 2] = __floats2half2_rn(a1.x + c0.w,  a1.y + c1.x);
                xh[cc * 4 + 3] = __floats2half2_rn(a1.z + c1.y,  a1.w + c1.z);
            }
        }

        // ---- GEMV: 6 rows, HFMA2 with fp32 flush every 8 terms ----
        float rs[6];
        #pragma unroll
        for (int r = 0; r < 6; r++) {
            __half2 acc = __float2half2_rn(0.f);
            float fx = 0.f, fy = 0.f;
            #pragma unroll
            for (int cc = 0; cc < 4; cc++) {
                __half2 w0, w1, w2, w3;
                if (r < 3) {
                    w0 = wreg[r][cc * 4];     w1 = wreg[r][cc * 4 + 1];
                    w2 = wreg[r][cc * 4 + 2]; w3 = wreg[r][cc * 4 + 3];
                } else {
                    const __half* wr = wsm2 + (warp * 3 + (r - 3)) * 1024 + cc * 256 + lane * 8;
                    uint4 u = *(const uint4*)wr;
                    w0 = *(__half2*)&u.x; w1 = *(__half2*)&u.y;
                    w2 = *(__half2*)&u.z; w3 = *(__half2*)&u.w;
                }
                acc = __hfma2(w0, xh[cc * 4], acc);
                acc = __hfma2(w1, xh[cc * 4 + 1], acc);
                acc = __hfma2(w2, xh[cc * 4 + 2], acc);
                acc = __hfma2(w3, xh[cc * 4 + 3], acc);
                if (cc & 1) {
                    fx += __low2float(acc); fy += __high2float(acc);
                    acc = __float2half2_rn(0.f);
                }
            }
            rs[r] = fx + fy;
        }
        #pragma unroll
        for (int r = 0; r < 6; r++)
            #pragma unroll
            for (int off = 16; off; off >>= 1)
                rs[r] += __shfl_xor_sync(0xffffffffu, rs[r], off);

        // ---- gates + store ----
        if (gate_lane && gidx_me < 2049) {
            float iR = (lane < 16) ? rs[0] : rs[3];
            float iZ = (lane < 16) ? rs[1] : rs[4];
            float iN = (lane < 16) ? rs[2] : rs[5];
            int rb = (lane >> 4) * 3;
            iR += bsm[warp * 6 + rb];
            iZ += bsm[warp * 6 + rb + 1];
            iN += bsm[warp * 6 + rb + 2];
            float rg = 1.f / (1.f + __expf(-(iR + ghR)));
            float zg = 1.f / (1.f + __expf(-(iZ + ghZ)));
            float ng = tanhf(iN + rg * ghN);
            float y = (1.f - zg) * ng + zg * hv;
            if (gidx_me < 1024)       out[(size_t)token * 2048 + gidx_me] = y;
            else if (gidx_me == 1024) g_yfx[token] = y;
            else                      out[(size_t)token * 2048 + gidx_me - 1] = y;
        }

        __syncthreads();
        if (tid == 0) red_rel_gpu(&bar[i]);
    }
}

extern "C" void kernel_launch(void* const* d_in, const int* in_sizes, int n_in,
                              void* d_out, int out_size)
{
    const float* e_q   = (const float*)d_in[0];
    const float* e_p   = (const float*)d_in[1];
    const float* f_s   = (const float*)d_in[2];
    const float* f_e   = (const float*)d_in[3];
    const float* Wih_f = (const float*)d_in[4];
    const float* Whh_f = (const float*)d_in[5];
    const float* bih_f = (const float*)d_in[6];
    const float* bhh_f = (const float*)d_in[7];
    const float* Wih_b = (const float*)d_in[8];
    const float* Whh_b = (const float*)d_in[9];
    const float* bih_b = (const float*)d_in[10];
    const float* bhh_b = (const float*)d_in[11];

    zero_bar_kernel<<<32, 256>>>();
    prep_h0_kernel<<<TT, NTHR>>>(e_q, e_p, f_s, f_e);
    prep_whh_kernel<<<2 * G3, NTHR>>>(Whh_f, Whh_b);
    gh_gemm_kernel<<<dim3(49, 36, 2), NTHR>>>(bhh_f, bhh_b);
    scan_kernel<<<2 * NC, NTHR>>>(Wih_f, Wih_b, bih_f, bih_b, (float*)d_out);
}